// round 7
// baseline (speedup 1.0000x reference)
#include <cuda_runtime.h>
#include <cuda_bf16.h>
#include <cstdint>

// Problem constants (fixed by the dataset)
#define BB  16
#define TT  128   // txt_T
#define MM  512   // mel_T
#define NC  80    // N_MEL

// k_logprob tiling
#define TBLK 32
#define MBLK 128
#define K1_THREADS 128

// chunked scan
#define NCH 16    // chunks
#define CS  32    // steps per chunk (covers m = 1..512; m>last predicated off)

// Scratch (no cudaMalloc allowed).
__device__ __align__(16) float g_elp[(size_t)BB * MM * TT + 4096]; // exp(lp), [b][m][t]
__device__ __align__(16) float g_band[(size_t)BB * NCH * 33 * 128]; // chunk band matrices
__device__ int   g_bandk[BB * NCH];             // per-chunk 2^k exponent
__device__ float g_alpha[BB];
__device__ unsigned g_cnt = 0;

// smem layout (bytes) for k_logprob
#define SM_X2_OFF 0
#define SM_X_OFF  (NC * 64 * 8)                 // 40960
#define SM_WA_OFF (SM_X_OFF + NC * 64 * 8)      // 81920
#define SM_KP_OFF (SM_WA_OFF + TBLK * NC * 8)   // 102400
#define SM_KC_OFF (SM_KP_OFF + TBLK * 4 * 4)    // 102912
#define SM_TOTAL  (SM_KC_OFF + TBLK * 4)        // 103040

// ---- packed f32x2 helpers (sm_103a dual-fp32 pipe; PTX-only) ----
__device__ __forceinline__ void fma2(unsigned long long& d,
                                     unsigned long long a,
                                     unsigned long long b) {
    asm("fma.rn.f32x2 %0, %1, %2, %0;" : "+l"(d) : "l"(a), "l"(b));
}
__device__ __forceinline__ unsigned long long pack2(float lo, float hi) {
    unsigned long long r;
    asm("mov.b64 %0, {%1, %2};" : "=l"(r) : "f"(lo), "f"(hi));
    return r;
}
__device__ __forceinline__ float2 unpack2(unsigned long long v) {
    float lo, hi;
    asm("mov.b64 {%0, %1}, %2;" : "=f"(lo), "=f"(hi) : "l"(v));
    return make_float2(lo, hi);
}

// ---------------------------------------------------------------------------
// Kernel 1: log_prob_matrix + exp(log_prob) scratch.  (unchanged, proven)
// ---------------------------------------------------------------------------
__global__ __launch_bounds__(K1_THREADS)
void k_logprob(const float* __restrict__ ml,     // [B, TT, 2*NC]
               const float* __restrict__ mel,    // [B, NC, MM]
               float* __restrict__ lpm)          // [B, TT, MM] (d_out + 1)
{
    extern __shared__ char sm[];
    unsigned long long* X2s = (unsigned long long*)(sm + SM_X2_OFF); // [NC][64]
    unsigned long long* Xs  = (unsigned long long*)(sm + SM_X_OFF);  // [NC][64]
    float2* wa = (float2*)(sm + SM_WA_OFF);  // [TBLK][NC] = {w, a}
    float*  kp = (float*) (sm + SM_KP_OFF);  // [TBLK][4]
    float*  kc = (float*) (sm + SM_KC_OFF);  // [TBLK]

    const int b   = blockIdx.z;
    const int t0  = blockIdx.y * TBLK;
    const int m0  = blockIdx.x * MBLK;
    const int tid = threadIdx.x;

    // Phase A: per-t coefficients. thread -> (t = tid/4, c-lane = tid%4)
    {
        const int t  = tid >> 2;
        const int cl = tid & 3;
        const float* row = ml + ((size_t)(b * TT + t0 + t)) * (2 * NC);
        float kpart = 0.f;
#pragma unroll
        for (int i = 0; i < 20; i++) {
            int c = cl + 4 * i;
            float mu = row[c];
            float lv = row[NC + c];
            float w  = __expf(-lv);
            float a  = -2.f * w * mu;
            wa[t * NC + c] = make_float2(w, a);
            kpart += __fmaf_rn(w * mu, mu, lv);
        }
        kp[t * 4 + cl] = kpart;
    }

    // Phase B: melspec tile -> packed (x2 pair) and (x pair)
    for (int lin = tid; lin < NC * 64; lin += K1_THREADS) {
        int c = lin >> 6;
        int p = lin & 63;
        float2 x = ((const float2*)(mel + ((size_t)(b * NC + c)) * MM + m0))[p];
        X2s[c * 64 + p] = pack2(x.x * x.x, x.y * x.y);
        Xs [c * 64 + p] = pack2(x.x, x.y);
    }
    __syncthreads();

    if (tid < TBLK) {
        kc[tid] = kp[tid*4] + kp[tid*4+1] + kp[tid*4+2] + kp[tid*4+3];
    }
    __syncthreads();

    // Phase C: FFMA2 micro-tile 4t x 4 m-pairs
    const int tx = tid & 15;     // m-pair lane
    const int ty = tid >> 4;     // t group (4 consecutive t)
    unsigned long long acc[4][4];
#pragma unroll
    for (int tt = 0; tt < 4; tt++)
#pragma unroll
        for (int j = 0; j < 4; j++) acc[tt][j] = 0ull;

#pragma unroll 2
    for (int c = 0; c < NC; c++) {
        unsigned long long x2p[4], xp[4];
#pragma unroll
        for (int j = 0; j < 4; j++) {
            x2p[j] = X2s[c * 64 + tx + 16 * j];
            xp[j]  = Xs [c * 64 + tx + 16 * j];
        }
#pragma unroll
        for (int tt = 0; tt < 4; tt++) {
            float2 wv = wa[(4 * ty + tt) * NC + c];
            unsigned long long ww = pack2(wv.x, wv.x);
            unsigned long long aa = pack2(wv.y, wv.y);
#pragma unroll
            for (int j = 0; j < 4; j++) {
                fma2(acc[tt][j], ww, x2p[j]);
                fma2(acc[tt][j], aa, xp[j]);
            }
        }
    }

    // Epilogue
    const float inv = -1.f / (2.f * NC);
    float kt[4];
#pragma unroll
    for (int tt = 0; tt < 4; tt++) kt[tt] = kc[4 * ty + tt];
    const int tg = t0 + 4 * ty;

#pragma unroll
    for (int j = 0; j < 4; j++) {
        const int me = m0 + 2 * (tx + 16 * j);   // even m
        float e0[4], e1[4];
#pragma unroll
        for (int tt = 0; tt < 4; tt++) {
            float2 v = unpack2(acc[tt][j]);
            float lp0 = (v.x + kt[tt]) * inv;
            float lp1 = (v.y + kt[tt]) * inv;
            float* dst = lpm + ((size_t)(b * TT + tg + tt)) * MM + me;
            dst[0] = lp0;          // d_out+1 is only 4B aligned: scalar stores
            dst[1] = lp1;
            e0[tt] = __expf(lp0);
            e1[tt] = __expf(lp1);
        }
        *(float4*)(g_elp + ((size_t)b * MM + me)     * TT + tg) =
            make_float4(e0[0], e0[1], e0[2], e0[3]);
        *(float4*)(g_elp + ((size_t)b * MM + me + 1) * TT + tg) =
            make_float4(e1[0], e1[1], e1[2], e1[3]);
    }
}

// ---------------------------------------------------------------------------
// Kernel 2a (k_band): build per-chunk banded transfer matrices, fully parallel.
// Chunk c applies steps m = 1+32c .. 32+32c (step active iff m <= mel_len-1).
// Thread j builds column j: band[k] = entry at row j+k (k=0..32), via
//   band[k] <- (band[k] + band[k-1]) * E[m][j+k]     (descending k)
// FIX vs round 6: block-uniform exact 2^e rescale every 8 steps (round-3
// lesson: 32 unrescaled steps underflow even the max path to fp32 zero).
// Matrix stored is 2^{-kc} * M_true; kc recorded in g_bandk[b][c].
// Output layout g_band[b][c][k][j] so k_combine reads coalesced.
// ---------------------------------------------------------------------------
__global__ __launch_bounds__(128)
void k_band(const int* __restrict__ mlen)
{
    __shared__ float Esm[CS][128];
    __shared__ float wred[4];
    const int c   = blockIdx.x;
    const int b   = blockIdx.y;
    const int tid = threadIdx.x;
    const int lane = tid & 31, wid = tid >> 5;
    const int last = mlen[b] - 1;
    const int m0   = 1 + c * CS;

    // stage E[m0..m0+31][0..127] into smem (g_elp is padded; m=512 row is
    // readable garbage and only touched when the step is inactive)
    {
        const float* Eb = g_elp + (size_t)b * MM * TT;
        float4* Ev4 = (float4*)Esm;
#pragma unroll
        for (int i = 0; i < 8; i++) {
            int lin = tid + 128 * i;        // float4 index
            int s = lin >> 5, t4 = lin & 31;
            Ev4[lin] = *(const float4*)(Eb + (size_t)(m0 + s) * TT + 4 * t4);
        }
    }
    __syncthreads();

    const int j = tid;
    float band[33];
    band[0] = 1.f;
#pragma unroll
    for (int k = 1; k <= 32; k++) band[k] = 0.f;
    int kc = 0;

#pragma unroll
    for (int s = 0; s < CS; s++) {
        // (m0+s) <= last is block-uniform (m0, last uniform per block)
        if ((m0 + s) <= last) {
#pragma unroll
            for (int k = 32; k >= 1; k--) {
                if (k <= s + 1) {                 // band extends to s+1 rows
                    int r = j + k; if (r > 127) r = 127;   // clamp (dead lanes)
                    band[k] = (band[k] + band[k - 1]) * Esm[s][r];
                }
            }
            band[0] *= Esm[s][j];
        }
        // exact 2^e block rescale every 8 steps (uniform control flow)
        if ((s & 7) == 7) {
            float mx = 0.f;
#pragma unroll
            for (int k = 0; k <= 32; k++) mx = fmaxf(mx, band[k]);
#pragma unroll
            for (int o = 16; o; o >>= 1)
                mx = fmaxf(mx, __shfl_xor_sync(0xffffffffu, mx, o));
            if (lane == 0) wred[wid] = mx;
            __syncthreads();
            mx = fmaxf(fmaxf(wred[0], wred[1]), fmaxf(wred[2], wred[3]));
            __syncthreads();            // protect wred before next overwrite
            if (mx > 0.f) {
                int eb = (__float_as_int(mx) >> 23) & 0xff;
                float sc = __int_as_float((254 - eb) << 23);
#pragma unroll
                for (int k = 0; k <= 32; k++) band[k] *= sc;
                kc += eb - 127;
            }
        }
    }

    float* dst = g_band + ((size_t)b * NCH + c) * 33 * 128;
#pragma unroll
    for (int k = 0; k <= 32; k++) dst[k * 128 + j] = band[k];
    if (tid == 0) g_bandk[b * NCH + c] = kc;
}

// ---------------------------------------------------------------------------
// Kernel 2b (k_combine): q <- M_c q for c = 0..15, exact 2^k rescale per
// chunk, then alpha extraction + fused loss reduction (proven ticket scheme).
// One block per batch, thread i owns row i. Bands prefetched 1 chunk ahead.
// Total exponent = per-chunk q rescales + per-chunk band exponents g_bandk.
// ---------------------------------------------------------------------------
__global__ __launch_bounds__(128)
void k_combine(float* __restrict__ out_base,     // d_out (out[0]=loss, +1=lpm)
               const int* __restrict__ tlen,
               const int* __restrict__ mlen)
{
    __shared__ float qs[128];
    __shared__ float wmax[4];
    const int b    = blockIdx.x;
    const int i    = threadIdx.x;
    const int lane = i & 31, wid = i >> 5;
    const int txt_len = tlen[b];
    const int mel_len = mlen[b];
    const float L0 = out_base[1 + (size_t)b * TT * MM];   // lp[b,0,0]

    qs[i] = (i == 0) ? 1.f : 0.f;
    int kTot = 0;

    const float* bb = g_band + (size_t)b * NCH * 33 * 128;
    float cur[33];
#pragma unroll
    for (int k = 0; k <= 32; k++) {
        int jc = i - k; if (jc < 0) jc = 0;
        cur[k] = bb[k * 128 + jc];
    }
    __syncthreads();

    for (int c = 0; c < NCH; c++) {
        // banded matvec row i: acc = sum_k M[i, i-k] * q[i-k]
        float a0 = 0.f, a1 = 0.f, a2 = 0.f, a3 = 0.f;
#pragma unroll
        for (int k = 0; k <= 32; k++) {
            int jc = i - k;
            float qv = (jc >= 0) ? qs[jc < 0 ? 0 : jc] : 0.f;
            float pr = cur[k] * qv;
            if ((k & 3) == 0) a0 += pr;
            else if ((k & 3) == 1) a1 += pr;
            else if ((k & 3) == 2) a2 += pr;
            else a3 += pr;
        }
        float acc = (a0 + a1) + (a2 + a3);

        // prefetch next chunk's band (independent of qs; hides L2 latency)
        if (c + 1 < NCH) {
            const float* nb = bb + (size_t)(c + 1) * 33 * 128;
#pragma unroll
            for (int k = 0; k <= 32; k++) {
                int jc = i - k; if (jc < 0) jc = 0;
                cur[k] = nb[k * 128 + jc];
            }
        }

        // block-wide exact 2^k rescale (uniform kTot)
        float s = acc;
#pragma unroll
        for (int o = 16; o; o >>= 1)
            s = fmaxf(s, __shfl_xor_sync(0xffffffffu, s, o));
        if (lane == 0) wmax[wid] = s;
        __syncthreads();                       // also orders qs reads vs writes
        s = fmaxf(fmaxf(wmax[0], wmax[1]), fmaxf(wmax[2], wmax[3]));
        float sc = 1.f;
        if (s > 0.f) {
            int eb = (__float_as_int(s) >> 23) & 0xff;
            sc = __int_as_float((254 - eb) << 23);
            kTot += eb - 127;
        }
        qs[i] = acc * sc;
        __syncthreads();
    }

    if (i == 0) {
        // fold in the band-matrix exponents
#pragma unroll
        for (int c = 0; c < NCH; c++) kTot += g_bandk[b * NCH + c];
        float v = qs[txt_len - 1];
        float alpha = __logf(v) + (float)kTot * 0.69314718055994531f + L0;
        g_alpha[b] = alpha / (float)mel_len;
        __threadfence();
        unsigned ticket = atomicAdd(&g_cnt, 1u);
        if (ticket == BB - 1) {
            __threadfence();
            float sum = 0.f;
#pragma unroll
            for (int k = 0; k < BB; k++)
                sum += ((volatile float*)g_alpha)[k];
            out_base[0] = -sum * (1.f / BB);
            g_cnt = 0;   // reset for next graph replay
        }
    }
}

// ---------------------------------------------------------------------------
extern "C" void kernel_launch(void* const* d_in, const int* in_sizes, int n_in,
                              void* d_out, int out_size)
{
    const float* ml  = (const float*)d_in[0];   // mu_logvar [16,128,160]
    const float* mel = (const float*)d_in[1];   // melspec   [16,80,512]
    const int*   tl  = (const int*)d_in[2];     // text_lengths [16]
    const int*   mll = (const int*)d_in[3];     // mel_lengths  [16]
    float* out = (float*)d_out;                 // [0]=loss, [1..]=log_prob_matrix

    cudaFuncSetAttribute(k_logprob,
                         cudaFuncAttributeMaxDynamicSharedMemorySize, SM_TOTAL);

    k_logprob<<<dim3(MM / MBLK, TT / TBLK, BB), K1_THREADS, SM_TOTAL>>>(
        ml, mel, out + 1);
    k_band<<<dim3(NCH, BB), 128>>>(mll);
    k_combine<<<BB, 128>>>(out, tl, mll);
}